// round 4
// baseline (speedup 1.0000x reference)
#include <cuda_runtime.h>
#include <cstdint>

#define L_DIM 2048
#define B_DIM 64
#define D_DEC 1024
#define D_ALIGN 512
#define D_ENC 1024
#define N_SPLIT 16
#define L_PER_SPLIT (L_DIM / N_SPLIT)   // 128

// ---- scratch ----
__device__ float g_proj[B_DIM * D_ALIGN];
__device__ float g_score[L_DIM * B_DIM];
__device__ float g_m[N_SPLIT * B_DIM];
__device__ float g_partial[N_SPLIT * B_DIM * D_ENC]; // 4 MB

__device__ __forceinline__ float tanh_approx(float x) {
    float y;
    asm("tanh.approx.f32 %0, %1;" : "=f"(y) : "f"(x));
    return y;
}

__device__ __forceinline__ float4 ldcs4(const float4* p) {
    float4 v;
    asm("ld.global.cs.v4.f32 {%0,%1,%2,%3}, [%4];"
        : "=f"(v.x), "=f"(v.y), "=f"(v.z), "=f"(v.w) : "l"(p));
    return v;
}

// ---- Kernel 1: proj = s_tm1 @ sa_w.T + sa_b, tiled 8a x 8b per block ----
__global__ __launch_bounds__(256) void k_proj(const float* __restrict__ s_tm1,
                                              const float* __restrict__ sa_w,
                                              const float* __restrict__ sa_b) {
    __shared__ float4 s_s[8][D_DEC / 4];
    int atile = blockIdx.x, btile = blockIdx.y;
    for (int i = threadIdx.x; i < 8 * (D_DEC / 4); i += 256) {
        int bb = i >> 8, idx = i & 255;
        s_s[bb][idx] = ((const float4*)(s_tm1 + (size_t)(btile * 8 + bb) * D_DEC))[idx];
    }
    __syncthreads();
    int warp = threadIdx.x >> 5, lane = threadIdx.x & 31;
    int a = atile * 8 + warp;
    const float4* wr = (const float4*)(sa_w + (size_t)a * D_DEC);
    float acc[8] = {0.f, 0.f, 0.f, 0.f, 0.f, 0.f, 0.f, 0.f};
#pragma unroll
    for (int it = 0; it < 8; it++) {
        float4 w4 = wr[lane + it * 32];
#pragma unroll
        for (int bb = 0; bb < 8; bb++) {
            float4 s4 = s_s[bb][lane + it * 32];
            acc[bb] = fmaf(w4.x, s4.x, acc[bb]);
            acc[bb] = fmaf(w4.y, s4.y, acc[bb]);
            acc[bb] = fmaf(w4.z, s4.z, acc[bb]);
            acc[bb] = fmaf(w4.w, s4.w, acc[bb]);
        }
    }
    float bias = sa_b[a];
#pragma unroll
    for (int bb = 0; bb < 8; bb++) {
        float v = acc[bb];
#pragma unroll
        for (int o = 16; o > 0; o >>= 1) v += __shfl_xor_sync(0xFFFFFFFFu, v, o);
        if (lane == 0) g_proj[(btile * 8 + bb) * D_ALIGN + a] = v + bias;
    }
}

// ---- Kernel 2 (fused): per (split,b) compute scores, split-local softmax
//      numerator, and partial attend accumulation ----
__global__ __launch_bounds__(256) void k_fused(const float* __restrict__ uh,
                                               const float* __restrict__ a1_w,
                                               const float* __restrict__ a1_b,
                                               const float* __restrict__ xs_mask,
                                               const float* __restrict__ xs_h) {
    __shared__ float4 s_proj[D_ALIGN / 4];
    __shared__ float4 s_w[D_ALIGN / 4];
    __shared__ float s_score[L_PER_SPLIT];
    __shared__ float s_wt[L_PER_SPLIT];
    __shared__ float red[128];
    int s = blockIdx.x, b = blockIdx.y;
    int tid = threadIdx.x;
    for (int i = tid; i < D_ALIGN / 4; i += 256) {
        s_proj[i] = ((const float4*)(g_proj + b * D_ALIGN))[i];
        s_w[i] = ((const float4*)a1_w)[i];
    }
    __syncthreads();
    int warp = tid >> 5, lane = tid & 31;
    float bias = a1_b[0];

    // Phase 1: 128 scores, warp-per-l, 16 iterations
#pragma unroll 2
    for (int it = 0; it < 16; it++) {
        int lloc = it * 8 + warp;
        int l = s * L_PER_SPLIT + lloc;
        const float4* row = (const float4*)(uh + ((size_t)(l * B_DIM + b)) * D_ALIGN);
        float sum = 0.0f;
#pragma unroll
        for (int j = 0; j < 4; j++) {
            int a4 = lane + j * 32;
            float4 u = ldcs4(row + a4);
            float4 p = s_proj[a4];
            float4 w = s_w[a4];
            sum = fmaf(tanh_approx(p.x + u.x), w.x, sum);
            sum = fmaf(tanh_approx(p.y + u.y), w.y, sum);
            sum = fmaf(tanh_approx(p.z + u.z), w.z, sum);
            sum = fmaf(tanh_approx(p.w + u.w), w.w, sum);
        }
#pragma unroll
        for (int o = 16; o > 0; o >>= 1) sum += __shfl_xor_sync(0xFFFFFFFFu, sum, o);
        if (lane == 0) s_score[lloc] = sum + bias;
    }
    __syncthreads();

    // split-local max
    if (tid < 128) red[tid] = s_score[tid];
    __syncthreads();
#pragma unroll
    for (int o = 64; o > 0; o >>= 1) {
        if (tid < o) red[tid] = fmaxf(red[tid], red[tid + o]);
        __syncthreads();
    }
    float m_s = red[0];
    // weights + spill scores
    if (tid < 128) {
        int l = s * L_PER_SPLIT + tid;
        float sc = s_score[tid];
        s_wt[tid] = __expf(sc - m_s) * xs_mask[l * B_DIM + b];
        g_score[l * B_DIM + b] = sc;
    }
    if (tid == 0) g_m[s * B_DIM + b] = m_s;
    __syncthreads();

    // Phase 2: weighted accumulation of xs_h rows
    float4 acc = make_float4(0.f, 0.f, 0.f, 0.f);
    const float4* base = (const float4*)xs_h;
    size_t idx = ((size_t)(s * L_PER_SPLIT * B_DIM + b)) * (D_ENC / 4) + tid;
#pragma unroll 4
    for (int i = 0; i < L_PER_SPLIT; i++) {
        float4 v = ldcs4(base + idx);
        float w = s_wt[i];
        acc.x = fmaf(w, v.x, acc.x);
        acc.y = fmaf(w, v.y, acc.y);
        acc.z = fmaf(w, v.z, acc.z);
        acc.w = fmaf(w, v.w, acc.w);
        idx += (size_t)B_DIM * (D_ENC / 4);
    }
    ((float4*)g_partial)[((s * B_DIM + b) * (D_ENC / 4)) + tid] = acc;
}

// ---- Kernel 3: finalize — global max/Z per b, write e_ij and attend ----
__global__ __launch_bounds__(256) void k_finalize(const float* __restrict__ xs_mask,
                                                  float* __restrict__ out) {
    __shared__ float red[256];
    int b = blockIdx.x;
    int tid = threadIdx.x;
    float loc[8], msk[8];
    float m = -1e30f;
#pragma unroll
    for (int i = 0; i < 8; i++) {
        int l = tid + i * 256;
        loc[i] = g_score[l * B_DIM + b];
        msk[i] = xs_mask[l * B_DIM + b];
        m = fmaxf(m, loc[i]);
    }
    red[tid] = m;
    __syncthreads();
#pragma unroll
    for (int o = 128; o > 0; o >>= 1) {
        if (tid < o) red[tid] = fmaxf(red[tid], red[tid + o]);
        __syncthreads();
    }
    m = red[0];
    __syncthreads();
    float e[8];
    float z = 0.0f;
#pragma unroll
    for (int i = 0; i < 8; i++) {
        e[i] = __expf(loc[i] - m) * msk[i];
        z += e[i];
    }
    red[tid] = z;
    __syncthreads();
#pragma unroll
    for (int o = 128; o > 0; o >>= 1) {
        if (tid < o) red[tid] += red[tid + o];
        __syncthreads();
    }
    float inv = 1.0f / red[0];
#pragma unroll
    for (int i = 0; i < 8; i++) out[(tid + i * 256) * B_DIM + b] = e[i] * inv;

    // attend: thread t -> float4 t of row b; rescale split partials
    float4 acc = make_float4(0.f, 0.f, 0.f, 0.f);
#pragma unroll
    for (int s = 0; s < N_SPLIT; s++) {
        float f = __expf(g_m[s * B_DIM + b] - m);
        float4 v = ((const float4*)g_partial)[((s * B_DIM + b) * (D_ENC / 4)) + tid];
        acc.x = fmaf(f, v.x, acc.x);
        acc.y = fmaf(f, v.y, acc.y);
        acc.z = fmaf(f, v.z, acc.z);
        acc.w = fmaf(f, v.w, acc.w);
    }
    acc.x *= inv; acc.y *= inv; acc.z *= inv; acc.w *= inv;
    ((float4*)(out + L_DIM * B_DIM))[b * (D_ENC / 4) + tid] = acc;
}

extern "C" void kernel_launch(void* const* d_in, const int* in_sizes, int n_in,
                              void* d_out, int out_size) {
    const float* s_tm1   = (const float*)d_in[0];
    const float* xs_h    = (const float*)d_in[1];
    const float* uh      = (const float*)d_in[2];
    const float* xs_mask = (const float*)d_in[3];
    const float* sa_w    = (const float*)d_in[4];
    const float* sa_b    = (const float*)d_in[5];
    const float* a1_w    = (const float*)d_in[6];
    const float* a1_b    = (const float*)d_in[7];
    float* out = (float*)d_out;

    dim3 g1(64, 8);
    k_proj<<<g1, 256>>>(s_tm1, sa_w, sa_b);
    dim3 g2(N_SPLIT, B_DIM);
    k_fused<<<g2, 256>>>(uh, a1_w, a1_b, xs_mask, xs_h);
    k_finalize<<<B_DIM, 256>>>(xs_mask, out);
}